// round 14
// baseline (speedup 1.0000x reference)
#include <cuda_runtime.h>
#include <math.h>
#include <stdint.h>

#define B_  2
#define S_  2048
#define E_  1024
#define H_  16
#define HD_ 64

// Scratch (allocation-free: __device__ globals)
__device__ float g_Q[B_*H_*S_*HD_];   // (b,h,s,d) tf32-rounded, scaled 0.125*log2(e)
__device__ float g_K[B_*H_*S_*HD_];   // (b,h,s,d) tf32-rounded, d 16-block-permuted
__device__ float g_V[B_*H_*S_*HD_];   // (b,h,d,s) TRANSPOSED, s 16-block-permuted
__device__ float g_O[B_*S_*E_];       // attention out, tf32-rounded, d 16-block-permuted
__device__ float g_Xr[B_*S_*E_];      // tf32-rounded x, k-chunk permuted
__device__ float g_Wq[3*E_*E_];       // tf32-rounded w_qkv, k-chunk permuted
__device__ float g_Wp[E_*E_];         // tf32-rounded w_proj, k-chunk permuted

// ============================================================================
// PTX helpers (plain sm_80+ ISA)
// ============================================================================
__device__ __forceinline__ float tf32_rna(float x) {
    uint32_t r;
    asm("cvt.rna.tf32.f32 %0, %1;" : "=r"(r) : "f"(x));
    return __uint_as_float(r);
}

__device__ __forceinline__ void mma_tf32(float4& d,
                                         uint32_t a0, uint32_t a1, uint32_t a2, uint32_t a3,
                                         uint32_t b0, uint32_t b1)
{
    asm volatile(
        "mma.sync.aligned.m16n8k8.row.col.f32.tf32.tf32.f32 "
        "{%0,%1,%2,%3}, {%4,%5,%6,%7}, {%8,%9}, {%0,%1,%2,%3};"
        : "+f"(d.x), "+f"(d.y), "+f"(d.z), "+f"(d.w)
        : "r"(a0), "r"(a1), "r"(a2), "r"(a3), "r"(b0), "r"(b1));
}

__device__ __forceinline__ uint32_t smem_u32(const void* p) {
    uint32_t a;
    asm("{ .reg .u64 tmp; cvta.to.shared.u64 tmp, %1; cvt.u32.u64 %0, tmp; }"
        : "=r"(a) : "l"(p));
    return a;
}

__device__ __forceinline__ void cp16(uint32_t dst, const void* src) {
    asm volatile("cp.async.cg.shared.global [%0], [%1], 16;"
                 :: "r"(dst), "l"(src) : "memory");
}
#define CP_COMMIT() asm volatile("cp.async.commit_group;" ::: "memory")
#define CP_WAIT0()  asm volatile("cp.async.wait_group 0;" ::: "memory")
#define CP_WAIT1()  asm volatile("cp.async.wait_group 1;" ::: "memory")

// exp2 on the FMA pipe: degree-6 poly on f in [-0.5, 0.5], rel err ~1.2e-7.
__device__ __forceinline__ float exp2p(float x) {
    x = fmaxf(x, -126.0f);
    float n = rintf(x);
    float f = x - n;
    float p = 1.5403530e-4f;
    p = fmaf(p, f, 1.3333558e-3f);
    p = fmaf(p, f, 9.6181291e-3f);
    p = fmaf(p, f, 5.5504109e-2f);
    p = fmaf(p, f, 2.4022651e-1f);
    p = fmaf(p, f, 6.9314718e-1f);
    p = fmaf(p, f, 1.0f);
    float s = __int_as_float(((int)n + 127) << 23);
    return p * s;
}

// pi(m) = (m%4)*4 + m/4 applied within a 16-aligned block (self-inverse)
__device__ __forceinline__ int perm16(int c) {
    return (c & ~15) + ((c & 3) * 4) + ((c & 15) >> 2);
}

// ============================================================================
// Pre-pass: tf32-round AND k-chunk-permute all three GEMM inputs.
// ============================================================================
#define N4_X  ((B_*S_*E_) / 4)
#define N4_WQ ((3*E_*E_) / 4)
#define N4_WP ((E_*E_) / 4)
#define N4_ALL (N4_X + N4_WQ + N4_WP)

__global__ void round_perm_all(const float* __restrict__ x,
                               const float* __restrict__ wq,
                               const float* __restrict__ wp)
{
    int f = blockIdx.x * blockDim.x + threadIdx.x;
    const int stride = gridDim.x * blockDim.x;
    for (; f < N4_ALL; f += stride) {
        const float* s;
        float4* d;
        int i = f;
        if (i < N4_X)               { s = x;  d = (float4*)g_Xr; }
        else if (i < N4_X + N4_WQ)  { i -= N4_X;         s = wq; d = (float4*)g_Wq; }
        else                        { i -= N4_X + N4_WQ; s = wp; d = (float4*)g_Wp; }
        const int t    = i & 3;
        const int base = (i >> 2) << 4;
        float4 v;
        v.x = tf32_rna(s[base + t]);
        v.y = tf32_rna(s[base + t + 4]);
        v.z = tf32_rna(s[base + t + 8]);
        v.w = tf32_rna(s[base + t + 12]);
        d[i] = v;
    }
}

// ============================================================================
// TF32 warp-MMA GEMM, FAT TILE: CTA 128(M) x 128(N), 8 warps 4m x 2n,
// warp tile 32x64. BK=32, 3-stage cp.async, one sync per chunk, 2 CTAs/SM.
// Stage = two 16-k halves, each [A 128x16 | B 128x16] = 4096 floats.
// Same operand values / k-pairing as round 10 -> bit-identical numerics.
// ============================================================================
#define GHALF 4096
#define GSTG  (2*GHALF)                 // 8192 floats per stage
#define GEMM_SMEM_BYTES (3*GSTG*4)      // 98304

__device__ __forceinline__ void gemm_fill32(uint32_t smu, const float* __restrict__ Ab,
                                            const float* __restrict__ Bb,
                                            int stage, int chunk, int tid)
{
#pragma unroll
    for (int j = 0; j < 8; j++) {
        const int o  = tid + 256 * j;     // 0..2047 float4 slots
        const int r  = o >> 3;            // 0..255 (A rows then B rows)
        const int q4 = o & 7;             // 8 float4 per row (2 halves)
        const int h  = q4 >> 2;
        const int q  = (q4 & 3) * 4;
        const float* src = (r < 128 ? Ab + (size_t)r * 1024
                                    : Bb + (size_t)(r - 128) * 1024)
                           + chunk * 32 + h * 16 + q;
        const uint32_t off = (uint32_t)(stage * GSTG + h * GHALF
                           + (r < 128 ? r * 16 : 2048 + (r - 128) * 16) + q);
        cp16(smu + off * 4, src);
    }
}

__device__ __forceinline__ void gemm_tf32_pipe32(const float* __restrict__ A,
                                                 const float* __restrict__ Bm,
                                                 int m0, int n0, float4 acc[2][8])
{
    extern __shared__ float sm[];
    const uint32_t smu = smem_u32(sm);
    const int tid  = threadIdx.x;
    const int lane = tid & 31;
    const int warp = tid >> 5;
    const int wm = (warp >> 1) * 32;   // 0,32,64,96
    const int wn = (warp & 1) * 64;    // 0,64
    const int g  = lane >> 2;
    const int t  = lane & 3;

    const float* Ab = A  + (size_t)m0 * 1024;
    const float* Bb = Bm + (size_t)n0 * 1024;

#pragma unroll
    for (int am = 0; am < 2; am++)
#pragma unroll
        for (int an = 0; an < 8; an++)
            acc[am][an] = make_float4(0.f, 0.f, 0.f, 0.f);

    gemm_fill32(smu, Ab, Bb, 0, 0, tid);
    CP_COMMIT();
    gemm_fill32(smu, Ab, Bb, 1, 1, tid);
    CP_COMMIT();

    int stage = 0;
    for (int c = 0; c < 32; ++c) {
        CP_WAIT1();
        __syncthreads();

        if (c + 2 < 32)
            gemm_fill32(smu, Ab, Bb, (stage + 2 >= 3 ? stage - 1 : stage + 2), c + 2, tid);
        CP_COMMIT();

#pragma unroll
        for (int h = 0; h < 2; h++) {
            const float* st = sm + stage * GSTG + h * GHALF;

            float4 vaL[2], vaH[2];
#pragma unroll
            for (int am = 0; am < 2; am++) {
                vaL[am] = *(const float4*)(st + (wm + am * 16 + g)     * 16 + 4 * t);
                vaH[am] = *(const float4*)(st + (wm + am * 16 + g + 8) * 16 + 4 * t);
            }

            // B fragments in two groups of 4 to bound live registers
#pragma unroll
            for (int grp = 0; grp < 2; grp++) {
                float4 vb[4];
#pragma unroll
                for (int ax = 0; ax < 4; ax++)
                    vb[ax] = *(const float4*)(st + 2048 + (wn + (grp * 4 + ax) * 8 + g) * 16 + 4 * t);
#pragma unroll
                for (int am = 0; am < 2; am++)
#pragma unroll
                    for (int ax = 0; ax < 4; ax++) {
                        mma_tf32(acc[am][grp * 4 + ax],
                                 __float_as_uint(vaL[am].x), __float_as_uint(vaH[am].x),
                                 __float_as_uint(vaL[am].y), __float_as_uint(vaH[am].y),
                                 __float_as_uint(vb[ax].x),  __float_as_uint(vb[ax].y));
                        mma_tf32(acc[am][grp * 4 + ax],
                                 __float_as_uint(vaL[am].z), __float_as_uint(vaH[am].z),
                                 __float_as_uint(vaL[am].w), __float_as_uint(vaH[am].w),
                                 __float_as_uint(vb[ax].z),  __float_as_uint(vb[ax].w));
                    }
            }
        }
        stage = (stage == 2) ? 0 : stage + 1;
    }
}

// ---------------------------------------------------------------------------
// Kernel 1: QKV GEMM. grid (24, 32). Q natural; K d-permuted; V transposed
// (b,h,d,s) s-permuted. Q pre-scaled by 0.125*log2(e).
// ---------------------------------------------------------------------------
#define QSCALE 0.18033688011112042f   // 0.125 * log2(e)

__global__ void __launch_bounds__(256, 2) qkv_mma()
{
    const int m0 = blockIdx.y * 128;
    const int n0 = blockIdx.x * 128;
    float4 acc[2][8];
    gemm_tf32_pipe32(g_Xr, g_Wq, m0, n0, acc);

    const int lane = threadIdx.x & 31;
    const int warp = threadIdx.x >> 5;
    const int wm = (warp >> 1) * 32;
    const int wn = (warp & 1) * 64;
    const int g  = lane >> 2;
    const int t  = lane & 3;

#pragma unroll
    for (int an = 0; an < 8; an++) {
        const int ng  = n0 + wn + an * 8;        // n = h*192 + sel*64 + d
        const int grp = ng >> 6;
        const int h   = grp / 3;
        const int sel = grp - 3 * h;
        const int d0  = (ng & 63) + t * 2;
        const float sc = (sel == 0) ? QSCALE : 1.0f;
#pragma unroll
        for (int am = 0; am < 2; am++) {
#pragma unroll
            for (int half = 0; half < 2; half++) {
                const int m = m0 + wm + am * 16 + g + half * 8;
                const int b = m >> 11;
                const int s = m & 2047;
                const float vx = tf32_rna((half ? acc[am][an].z : acc[am][an].x) * sc);
                const float vy = tf32_rna((half ? acc[am][an].w : acc[am][an].y) * sc);
                const size_t bh = (size_t)(b * 16 + h);
                if (sel == 0) {
                    *(float2*)(g_Q + (bh * 2048 + s) * 64 + d0) = make_float2(vx, vy);
                } else if (sel == 1) {
                    float* kp = g_K + (bh * 2048 + s) * 64;
                    kp[perm16(d0)]     = vx;
                    kp[perm16(d0 + 1)] = vy;
                } else {
                    const int sp = perm16(s);
                    float* vp = g_V + (bh * 64 + d0) * 2048;
                    vp[sp]        = vx;
                    vp[2048 + sp] = vy;
                }
            }
        }
    }
}

// ---------------------------------------------------------------------------
// Kernel 3: output projection. grid (8, 32).
// ---------------------------------------------------------------------------
__global__ void __launch_bounds__(256, 2) proj_mma(const float* __restrict__ bias,
                                                   float* __restrict__ out)
{
    const int m0 = blockIdx.y * 128;
    const int n0 = blockIdx.x * 128;
    float4 acc[2][8];
    gemm_tf32_pipe32(g_O, g_Wp, m0, n0, acc);

    const int lane = threadIdx.x & 31;
    const int warp = threadIdx.x >> 5;
    const int wm = (warp >> 1) * 32;
    const int wn = (warp & 1) * 64;
    const int g  = lane >> 2;
    const int t  = lane & 3;

#pragma unroll
    for (int an = 0; an < 8; an++) {
        const int ng = n0 + wn + an * 8 + t * 2;
        const float2 bi = *(const float2*)(bias + ng);
#pragma unroll
        for (int am = 0; am < 2; am++) {
#pragma unroll
            for (int half = 0; half < 2; half++) {
                const int m = m0 + wm + am * 16 + g + half * 8;
                float2 v;
                v.x = (half ? acc[am][an].z : acc[am][an].x) + bi.x;
                v.y = (half ? acc[am][an].w : acc[am][an].y) + bi.y;
                *(float2*)(out + (size_t)m * 1024 + ng) = v;
            }
        }
    }
}

// ============================================================================
// Kernel 2: tensor-core causal flash attention — EXACT round-12 body
// (best known: pairs of 64-col kv-tiles, 2 pair-buffers, one barrier/pair).
// ============================================================================
#define KVSTR 80
#define TILEF (64*KVSTR)
#define PAIRB (2*TILEF)
#define OFF_V (2*PAIRB)
#define OFF_P (OFF_V + 2*PAIRB)
#define PSTRD 68
#define FA_SMEM_BYTES ((OFF_P + 128*PSTRD) * 4)   // 198656

__global__ void __launch_bounds__(256, 1) flash_attn_tc()
{
    extern __shared__ float sm[];
    const uint32_t smu = smem_u32(sm);
    const int tid  = threadIdx.x;
    const int lane = tid & 31;
    const int warp = tid >> 5;
    const int g  = lane >> 2;
    const int t4 = lane & 3;
    const int qt = 15 - (int)blockIdx.x;
    const int bh = blockIdx.y;
    const int q0 = qt * 128;
    const int wr = warp * 16;
    const int npair = qt + 1;

    const float* Qg = g_Q + (size_t)bh * S_ * 64;
    const float* Kg = g_K + (size_t)bh * S_ * 64;
    const float* Vg = g_V + (size_t)bh * 64 * S_;

    const int fr = tid >> 2;
    const int fc = (tid & 3) * 16;

#pragma unroll
    for (int u = 0; u < 2; u++) {
        const int kv = u * 64;
        const float* ks = Kg + (size_t)(kv + fr) * 64 + fc;
        const float* vs = Vg + (size_t)fr * 2048 + kv + fc;
        const uint32_t kd = smu + (uint32_t)(u * TILEF + fr * KVSTR + fc) * 4;
        const uint32_t vd = smu + (uint32_t)(OFF_V + u * TILEF + fr * KVSTR + fc) * 4;
#pragma unroll
        for (int j = 0; j < 4; j++) {
            cp16(kd + j * 16, ks + j * 4);
            cp16(vd + j * 16, vs + j * 4);
        }
    }
    CP_COMMIT();

    {
        const int r  = tid >> 1;
        const int c0 = (tid & 1) * 32;
        const float* src = Qg + (size_t)(q0 + r) * 64 + c0;
        float* dst = sm + OFF_P + r * PSTRD + c0;
#pragma unroll
        for (int j = 0; j < 8; j++)
            *(float4*)(dst + j * 4) = *(const float4*)(src + j * 4);
    }
    __syncthreads();

    uint32_t qf[8][4];
#pragma unroll
    for (int kk = 0; kk < 8; kk++) {
        const float* p = sm + OFF_P + (wr + g) * PSTRD + kk * 8 + t4;
        qf[kk][0] = __float_as_uint(p[0]);
        qf[kk][1] = __float_as_uint(p[8 * PSTRD]);
        qf[kk][2] = __float_as_uint(p[4]);
        qf[kk][3] = __float_as_uint(p[8 * PSTRD + 4]);
    }

    float m2[2] = {-1e30f, -1e30f};
    float l2[2] = {0.f, 0.f};
    float4 of[8];
#pragma unroll
    for (int an = 0; an < 8; an++) of[an] = make_float4(0.f, 0.f, 0.f, 0.f);

    for (int pp = 0; pp < npair; pp++) {
        CP_WAIT0();
        __syncthreads();

        if (pp + 1 < npair) {
            const int pb = (pp + 1) & 1;
#pragma unroll
            for (int u = 0; u < 2; u++) {
                const int kv = (pp + 1) * 128 + u * 64;
                const float* ks = Kg + (size_t)(kv + fr) * 64 + fc;
                const float* vs = Vg + (size_t)fr * 2048 + kv + fc;
                const uint32_t kd = smu + (uint32_t)(pb * PAIRB + u * TILEF + fr * KVSTR + fc) * 4;
                const uint32_t vd = smu + (uint32_t)(OFF_V + pb * PAIRB + u * TILEF + fr * KVSTR + fc) * 4;
#pragma unroll
                for (int j = 0; j < 4; j++) {
                    cp16(kd + j * 16, ks + j * 4);
                    cp16(vd + j * 16, vs + j * 4);
                }
            }
        }
        CP_COMMIT();

#pragma unroll
        for (int u = 0; u < 2; u++) {
            const int t   = 2 * pp + u;
            const int kv0 = t * 64;
            if (kv0 > q0 + wr + 15) continue;

            const float* smK = sm + (pp & 1) * PAIRB + u * TILEF;
            const float* smV = sm + OFF_V + (pp & 1) * PAIRB + u * TILEF;

            float4 sf[8];
#pragma unroll
            for (int an = 0; an < 8; an++) sf[an] = make_float4(0.f, 0.f, 0.f, 0.f);
#pragma unroll
            for (int b = 0; b < 4; b++) {
#pragma unroll
                for (int an = 0; an < 8; an++) {
                    const float4 kv4 = *(const float4*)(smK + (an * 8 + g) * KVSTR + 16 * b + 4 * t4);
                    mma_tf32(sf[an], qf[2*b][0], qf[2*b][1], qf[2*b][2], qf[2*b][3],
                             __float_as_uint(kv4.x), __float_as_uint(kv4.y));
                    mma_tf32(sf[an], qf[2*b+1][0], qf[2*b+1][1], qf[2*b+1][2], qf[2*b+1][3],
                             __float_as_uint(kv4.z), __float_as_uint(kv4.w));
                }
            }

            if (kv0 + 63 > q0 + wr) {
                const int r0 = q0 + wr + g;
                const int r1 = r0 + 8;
#pragma unroll
                for (int an = 0; an < 8; an++) {
                    const int col = kv0 + an * 8 + 2 * t4;
                    if (col     > r0) sf[an].x = -1e30f;
                    if (col + 1 > r0) sf[an].y = -1e30f;
                    if (col     > r1) sf[an].z = -1e30f;
                    if (col + 1 > r1) sf[an].w = -1e30f;
                }
            }

            float mt0 = -1e30f, mt1 = -1e30f;
#pragma unroll
            for (int an = 0; an < 8; an++) {
                mt0 = fmaxf(mt0, fmaxf(sf[an].x, sf[an].y));
                mt1 = fmaxf(mt1, fmaxf(sf[an].z, sf[an].w));
            }
            mt0 = fmaxf(mt0, __shfl_xor_sync(0xffffffffu, mt0, 1));
            mt0 = fmaxf(mt0, __shfl_xor_sync(0xffffffffu, mt0, 2));
            mt1 = fmaxf(mt1, __shfl_xor_sync(0xffffffffu, mt1, 1));
            mt1 = fmaxf(mt1, __shfl_xor_sync(0xffffffffu, mt1, 2));

            const float mn0 = fmaxf(m2[0], mt0);
            const float mn1 = fmaxf(m2[1], mt1);
            const float a0 = exp2p(m2[0] - mn0);
            const float a1 = exp2p(m2[1] - mn1);
            m2[0] = mn0; m2[1] = mn1;

            float s0 = 0.f, s1 = 0.f;
#pragma unroll
            for (int an = 0; an < 8; an++) {
                sf[an].x = tf32_rna(exp2p(sf[an].x - mn0));
                sf[an].y = tf32_rna(exp2p(sf[an].y - mn0));
                sf[an].z = tf32_rna(exp2p(sf[an].z - mn1));
                sf[an].w = tf32_rna(exp2p(sf[an].w - mn1));
                s0 += sf[an].x + sf[an].y;
                s1 += sf[an].z + sf[an].w;
            }
            s0 += __shfl_xor_sync(0xffffffffu, s0, 1);
            s0 += __shfl_xor_sync(0xffffffffu, s0, 2);
            s1 += __shfl_xor_sync(0xffffffffu, s1, 1);
            s1 += __shfl_xor_sync(0xffffffffu, s1, 2);
            l2[0] = l2[0] * a0 + s0;
            l2[1] = l2[1] * a1 + s1;

#pragma unroll
            for (int an = 0; an < 8; an++) {
                of[an].x *= a0; of[an].y *= a0;
                of[an].z *= a1; of[an].w *= a1;
            }

            {
                float* pp2 = sm + OFF_P + (wr + g) * PSTRD;
#pragma unroll
                for (int an = 0; an < 8; an++) {
                    *(float2*)(pp2 + an * 8 + 2 * t4) = make_float2(sf[an].x, sf[an].y);
                    *(float2*)(pp2 + 8 * PSTRD + an * 8 + 2 * t4) = make_float2(sf[an].z, sf[an].w);
                }
            }
            __syncwarp();

#pragma unroll
            for (int b = 0; b < 4; b++) {
                const float* ap = sm + OFF_P + (wr + g) * PSTRD + 16 * b + t4;
                const uint32_t A00 = __float_as_uint(ap[0]);
                const uint32_t A01 = __float_as_uint(ap[8 * PSTRD]);
                const uint32_t A02 = __float_as_uint(ap[4]);
                const uint32_t A03 = __float_as_uint(ap[8 * PSTRD + 4]);
                const uint32_t A10 = __float_as_uint(ap[8]);
                const uint32_t A11 = __float_as_uint(ap[8 * PSTRD + 8]);
                const uint32_t A12 = __float_as_uint(ap[12]);
                const uint32_t A13 = __float_as_uint(ap[8 * PSTRD + 12]);
#pragma unroll
                for (int an = 0; an < 8; an++) {
                    const float4 vv = *(const float4*)(smV + (an * 8 + g) * KVSTR + 16 * b + 4 * t4);
                    mma_tf32(of[an], A00, A01, A02, A03,
                             __float_as_uint(vv.x), __float_as_uint(vv.y));
                    mma_tf32(of[an], A10, A11, A12, A13,
                             __float_as_uint(vv.z), __float_as_uint(vv.w));
                }
            }
        }
    }

    const int b = bh >> 4;
    const int h = bh & 15;
    const float i0 = 1.0f / l2[0];
    const float i1 = 1.0f / l2[1];
    const int r0 = q0 + wr + g;
    const int r1 = r0 + 8;
    float* o0 = g_O + ((size_t)b * 2048 + r0) * 1024 + h * 64;
    float* o1 = g_O + ((size_t)b * 2048 + r1) * 1024 + h * 64;
#pragma unroll
    for (int an = 0; an < 8; an++) {
        const int c0 = an * 8 + 2 * t4;
        const int p0 = perm16(c0);
        const int p1 = perm16(c0 + 1);
        o0[p0] = tf32_rna(of[an].x * i0);
        o0[p1] = tf32_rna(of[an].y * i0);
        o1[p0] = tf32_rna(of[an].z * i1);
        o1[p1] = tf32_rna(of[an].w * i1);
    }
}

// ---------------------------------------------------------------------------
extern "C" void kernel_launch(void* const* d_in, const int* in_sizes, int n_in,
                              void* d_out, int out_size)
{
    const float* x      = (const float*)d_in[0];  // (2,2048,1024)
    const float* w_qkv  = (const float*)d_in[1];  // (3072,1024)
    const float* w_proj = (const float*)d_in[2];  // (1024,1024)
    const float* b_proj = (const float*)d_in[3];  // (1024,)
    float* out = (float*)d_out;

    cudaFuncSetAttribute(flash_attn_tc, cudaFuncAttributeMaxDynamicSharedMemorySize,
                         FA_SMEM_BYTES);
    cudaFuncSetAttribute(qkv_mma, cudaFuncAttributeMaxDynamicSharedMemorySize,
                         GEMM_SMEM_BYTES);
    cudaFuncSetAttribute(proj_mma, cudaFuncAttributeMaxDynamicSharedMemorySize,
                         GEMM_SMEM_BYTES);

    round_perm_all<<<592, 256>>>(x, w_qkv, w_proj);

    qkv_mma<<<dim3(24, 32), 256, GEMM_SMEM_BYTES>>>();
    flash_attn_tc<<<dim3(16, 32), 256, FA_SMEM_BYTES>>>();
    proj_mma<<<dim3(8, 32), 256, GEMM_SMEM_BYTES>>>(b_proj, out);
}

// round 15
// speedup vs baseline: 1.0329x; 1.0329x over previous
#include <cuda_runtime.h>
#include <math.h>
#include <stdint.h>

#define B_  2
#define S_  2048
#define E_  1024
#define H_  16
#define HD_ 64

// Scratch (allocation-free: __device__ globals)
__device__ float g_Q[B_*H_*S_*HD_];   // (b,h,s,d) tf32-rounded, scaled 0.125*log2(e)
__device__ float g_K[B_*H_*S_*HD_];   // (b,h,s,d) tf32-rounded, d 16-block-permuted
__device__ float g_V[B_*H_*S_*HD_];   // (b,h,d,s) TRANSPOSED, s 16-block-permuted
__device__ float g_O[B_*S_*E_];       // attention out, tf32-rounded, d 16-block-permuted
__device__ float g_Xr[B_*S_*E_];      // tf32-rounded x, k-chunk permuted
__device__ float g_Wq[3*E_*E_];       // tf32-rounded w_qkv, k-chunk permuted
__device__ float g_Wp[E_*E_];         // tf32-rounded w_proj, k-chunk permuted

// ============================================================================
// PTX helpers (plain sm_80+ ISA)
// ============================================================================
__device__ __forceinline__ float tf32_rna(float x) {
    uint32_t r;
    asm("cvt.rna.tf32.f32 %0, %1;" : "=r"(r) : "f"(x));
    return __uint_as_float(r);
}

__device__ __forceinline__ void mma_tf32(float4& d,
                                         uint32_t a0, uint32_t a1, uint32_t a2, uint32_t a3,
                                         uint32_t b0, uint32_t b1)
{
    asm volatile(
        "mma.sync.aligned.m16n8k8.row.col.f32.tf32.tf32.f32 "
        "{%0,%1,%2,%3}, {%4,%5,%6,%7}, {%8,%9}, {%0,%1,%2,%3};"
        : "+f"(d.x), "+f"(d.y), "+f"(d.z), "+f"(d.w)
        : "r"(a0), "r"(a1), "r"(a2), "r"(a3), "r"(b0), "r"(b1));
}

__device__ __forceinline__ uint32_t smem_u32(const void* p) {
    uint32_t a;
    asm("{ .reg .u64 tmp; cvta.to.shared.u64 tmp, %1; cvt.u32.u64 %0, tmp; }"
        : "=r"(a) : "l"(p));
    return a;
}

__device__ __forceinline__ void cp16(uint32_t dst, const void* src) {
    asm volatile("cp.async.cg.shared.global [%0], [%1], 16;"
                 :: "r"(dst), "l"(src) : "memory");
}
#define CP_COMMIT() asm volatile("cp.async.commit_group;" ::: "memory")
#define CP_WAIT0()  asm volatile("cp.async.wait_group 0;" ::: "memory")
#define CP_WAIT1()  asm volatile("cp.async.wait_group 1;" ::: "memory")

// exp2 on the FMA pipe: degree-6 poly on f in [-0.5, 0.5], rel err ~1.2e-7.
__device__ __forceinline__ float exp2p(float x) {
    x = fmaxf(x, -126.0f);
    float n = rintf(x);
    float f = x - n;
    float p = 1.5403530e-4f;
    p = fmaf(p, f, 1.3333558e-3f);
    p = fmaf(p, f, 9.6181291e-3f);
    p = fmaf(p, f, 5.5504109e-2f);
    p = fmaf(p, f, 2.4022651e-1f);
    p = fmaf(p, f, 6.9314718e-1f);
    p = fmaf(p, f, 1.0f);
    float s = __int_as_float(((int)n + 127) << 23);
    return p * s;
}

// pi(m) = (m%4)*4 + m/4 applied within a 16-aligned block (self-inverse)
__device__ __forceinline__ int perm16(int c) {
    return (c & ~15) + ((c & 3) * 4) + ((c & 15) >> 2);
}

// ============================================================================
// Pre-pass: tf32-round AND k-chunk-permute all three GEMM inputs.
// ============================================================================
#define N4_X  ((B_*S_*E_) / 4)
#define N4_WQ ((3*E_*E_) / 4)
#define N4_WP ((E_*E_) / 4)
#define N4_ALL (N4_X + N4_WQ + N4_WP)

__global__ void round_perm_all(const float* __restrict__ x,
                               const float* __restrict__ wq,
                               const float* __restrict__ wp)
{
    int f = blockIdx.x * blockDim.x + threadIdx.x;
    const int stride = gridDim.x * blockDim.x;
    for (; f < N4_ALL; f += stride) {
        const float* s;
        float4* d;
        int i = f;
        if (i < N4_X)               { s = x;  d = (float4*)g_Xr; }
        else if (i < N4_X + N4_WQ)  { i -= N4_X;         s = wq; d = (float4*)g_Wq; }
        else                        { i -= N4_X + N4_WQ; s = wp; d = (float4*)g_Wp; }
        const int t    = i & 3;
        const int base = (i >> 2) << 4;
        float4 v;
        v.x = tf32_rna(s[base + t]);
        v.y = tf32_rna(s[base + t + 4]);
        v.z = tf32_rna(s[base + t + 8]);
        v.w = tf32_rna(s[base + t + 12]);
        d[i] = v;
    }
}

// ============================================================================
// GEMM variant A (qkv, round-12 verified): CTA 128x64, 8 warps 4m x 2n,
// warp 32x32, BK=32, 3-stage cp.async, one sync per chunk, 3 CTAs/SM.
// ============================================================================
#define HALF_F 3072
#define STGF32 (2*HALF_F)
#define QKV_SMEM_BYTES (3*STGF32*4)   // 73728

__device__ __forceinline__ void qkv_fill32(uint32_t smu, const float* __restrict__ Ab,
                                           const float* __restrict__ Bb,
                                           int stage, int chunk, int tid)
{
#pragma unroll
    for (int j = 0; j < 6; j++) {
        const int o = tid + 256 * j;
        const int h = (o >> 2) & 1;
        const int r = o >> 3;
        const int q = (o & 3) * 4;
        const float* src;
        uint32_t off;
        if (r < 128) {
            src = Ab + (size_t)r * 1024 + chunk * 32 + h * 16 + q;
            off = (uint32_t)(r * 16);
        } else {
            src = Bb + (size_t)(r - 128) * 1024 + chunk * 32 + h * 16 + q;
            off = (uint32_t)(2048 + (r - 128) * 16);
        }
        cp16(smu + (uint32_t)(stage * STGF32 + h * HALF_F + off + q) * 4, src);
    }
}

#define QSCALE 0.18033688011112042f   // 0.125 * log2(e)

__global__ void __launch_bounds__(256, 3) qkv_mma()
{
    extern __shared__ float sm[];
    const uint32_t smu = smem_u32(sm);
    const int tid  = threadIdx.x;
    const int lane = tid & 31;
    const int warp = tid >> 5;
    const int wm = (warp >> 1) * 32;
    const int wn = (warp & 1) * 32;
    const int g  = lane >> 2;
    const int t  = lane & 3;
    const int m0 = blockIdx.y * 128;
    const int n0 = blockIdx.x * 64;

    const float* Ab = g_Xr + (size_t)m0 * 1024;
    const float* Bb = g_Wq + (size_t)n0 * 1024;

    float4 acc[2][4];
#pragma unroll
    for (int am = 0; am < 2; am++)
#pragma unroll
        for (int an = 0; an < 4; an++)
            acc[am][an] = make_float4(0.f, 0.f, 0.f, 0.f);

    qkv_fill32(smu, Ab, Bb, 0, 0, tid);
    CP_COMMIT();
    qkv_fill32(smu, Ab, Bb, 1, 1, tid);
    CP_COMMIT();

    int stage = 0;
    for (int c = 0; c < 32; ++c) {
        CP_WAIT1();
        __syncthreads();

        if (c + 2 < 32)
            qkv_fill32(smu, Ab, Bb, (stage + 2 >= 3 ? stage - 1 : stage + 2), c + 2, tid);
        CP_COMMIT();

#pragma unroll
        for (int h = 0; h < 2; h++) {
            const float* st = sm + stage * STGF32 + h * HALF_F;

            float4 vb[4];
#pragma unroll
            for (int an = 0; an < 4; an++)
                vb[an] = *(const float4*)(st + 2048 + (wn + an * 8 + g) * 16 + 4 * t);

            float4 vaL[2], vaH[2];
#pragma unroll
            for (int am = 0; am < 2; am++) {
                vaL[am] = *(const float4*)(st + (wm + am * 16 + g)     * 16 + 4 * t);
                vaH[am] = *(const float4*)(st + (wm + am * 16 + g + 8) * 16 + 4 * t);
            }
#pragma unroll
            for (int am = 0; am < 2; am++)
#pragma unroll
                for (int an = 0; an < 4; an++) {
                    mma_tf32(acc[am][an],
                             __float_as_uint(vaL[am].x), __float_as_uint(vaH[am].x),
                             __float_as_uint(vaL[am].y), __float_as_uint(vaH[am].y),
                             __float_as_uint(vb[an].x),  __float_as_uint(vb[an].y));
                    mma_tf32(acc[am][an],
                             __float_as_uint(vaL[am].z), __float_as_uint(vaH[am].z),
                             __float_as_uint(vaL[am].w), __float_as_uint(vaH[am].w),
                             __float_as_uint(vb[an].z),  __float_as_uint(vb[an].w));
                }
        }
        stage = (stage == 2) ? 0 : stage + 1;
    }

    // epilogue: Q natural; K d-permuted; V transposed (b,h,d,s) s-permuted
#pragma unroll
    for (int an = 0; an < 4; an++) {
        const int ng  = n0 + wn + an * 8;        // n = h*192 + sel*64 + d
        const int grp = ng >> 6;
        const int h   = grp / 3;
        const int sel = grp - 3 * h;
        const int d0  = (ng & 63) + t * 2;
        const float sc = (sel == 0) ? QSCALE : 1.0f;
#pragma unroll
        for (int am = 0; am < 2; am++) {
#pragma unroll
            for (int half = 0; half < 2; half++) {
                const int m = m0 + wm + am * 16 + g + half * 8;
                const int b = m >> 11;
                const int s = m & 2047;
                const float vx = tf32_rna((half ? acc[am][an].z : acc[am][an].x) * sc);
                const float vy = tf32_rna((half ? acc[am][an].w : acc[am][an].y) * sc);
                const size_t bh = (size_t)(b * 16 + h);
                if (sel == 0) {
                    *(float2*)(g_Q + (bh * 2048 + s) * 64 + d0) = make_float2(vx, vy);
                } else if (sel == 1) {
                    float* kp = g_K + (bh * 2048 + s) * 64;
                    kp[perm16(d0)]     = vx;
                    kp[perm16(d0 + 1)] = vy;
                } else {
                    const int sp = perm16(s);
                    float* vp = g_V + (bh * 64 + d0) * 2048;
                    vp[sp]        = vx;
                    vp[2048 + sp] = vy;
                }
            }
        }
    }
}

// ============================================================================
// GEMM variant B (proj, round-14 verified faster for proj): CTA 128x128,
// 8 warps 4m x 2n, warp 32x64, BK=32, 3-stage, 2 CTAs/SM. grid (8,32) = one
// wave at 2/SM.
// ============================================================================
#define GHALF 4096
#define GSTG  (2*GHALF)
#define PROJ_SMEM_BYTES (3*GSTG*4)      // 98304

__device__ __forceinline__ void proj_fill32(uint32_t smu, const float* __restrict__ Ab,
                                            const float* __restrict__ Bb,
                                            int stage, int chunk, int tid)
{
#pragma unroll
    for (int j = 0; j < 8; j++) {
        const int o  = tid + 256 * j;
        const int r  = o >> 3;
        const int q4 = o & 7;
        const int h  = q4 >> 2;
        const int q  = (q4 & 3) * 4;
        const float* src = (r < 128 ? Ab + (size_t)r * 1024
                                    : Bb + (size_t)(r - 128) * 1024)
                           + chunk * 32 + h * 16 + q;
        const uint32_t off = (uint32_t)(stage * GSTG + h * GHALF
                           + (r < 128 ? r * 16 : 2048 + (r - 128) * 16) + q);
        cp16(smu + off * 4, src);
    }
}

__global__ void __launch_bounds__(256, 2) proj_mma(const float* __restrict__ bias,
                                                   float* __restrict__ out)
{
    extern __shared__ float sm[];
    const uint32_t smu = smem_u32(sm);
    const int tid  = threadIdx.x;
    const int lane = tid & 31;
    const int warp = tid >> 5;
    const int wm = (warp >> 1) * 32;
    const int wn = (warp & 1) * 64;
    const int g  = lane >> 2;
    const int t  = lane & 3;
    const int m0 = blockIdx.y * 128;
    const int n0 = blockIdx.x * 128;

    const float* Ab = g_O  + (size_t)m0 * 1024;
    const float* Bb = g_Wp + (size_t)n0 * 1024;

    float4 acc[2][8];
#pragma unroll
    for (int am = 0; am < 2; am++)
#pragma unroll
        for (int an = 0; an < 8; an++)
            acc[am][an] = make_float4(0.f, 0.f, 0.f, 0.f);

    proj_fill32(smu, Ab, Bb, 0, 0, tid);
    CP_COMMIT();
    proj_fill32(smu, Ab, Bb, 1, 1, tid);
    CP_COMMIT();

    int stage = 0;
    for (int c = 0; c < 32; ++c) {
        CP_WAIT1();
        __syncthreads();

        if (c + 2 < 32)
            proj_fill32(smu, Ab, Bb, (stage + 2 >= 3 ? stage - 1 : stage + 2), c + 2, tid);
        CP_COMMIT();

#pragma unroll
        for (int h = 0; h < 2; h++) {
            const float* st = sm + stage * GSTG + h * GHALF;

            float4 vaL[2], vaH[2];
#pragma unroll
            for (int am = 0; am < 2; am++) {
                vaL[am] = *(const float4*)(st + (wm + am * 16 + g)     * 16 + 4 * t);
                vaH[am] = *(const float4*)(st + (wm + am * 16 + g + 8) * 16 + 4 * t);
            }

#pragma unroll
            for (int grp = 0; grp < 2; grp++) {
                float4 vb[4];
#pragma unroll
                for (int ax = 0; ax < 4; ax++)
                    vb[ax] = *(const float4*)(st + 2048 + (wn + (grp * 4 + ax) * 8 + g) * 16 + 4 * t);
#pragma unroll
                for (int am = 0; am < 2; am++)
#pragma unroll
                    for (int ax = 0; ax < 4; ax++) {
                        mma_tf32(acc[am][grp * 4 + ax],
                                 __float_as_uint(vaL[am].x), __float_as_uint(vaH[am].x),
                                 __float_as_uint(vaL[am].y), __float_as_uint(vaH[am].y),
                                 __float_as_uint(vb[ax].x),  __float_as_uint(vb[ax].y));
                        mma_tf32(acc[am][grp * 4 + ax],
                                 __float_as_uint(vaL[am].z), __float_as_uint(vaH[am].z),
                                 __float_as_uint(vaL[am].w), __float_as_uint(vaH[am].w),
                                 __float_as_uint(vb[ax].z),  __float_as_uint(vb[ax].w));
                    }
            }
        }
        stage = (stage == 2) ? 0 : stage + 1;
    }

#pragma unroll
    for (int an = 0; an < 8; an++) {
        const int ng = n0 + wn + an * 8 + t * 2;
        const float2 bi = *(const float2*)(bias + ng);
#pragma unroll
        for (int am = 0; am < 2; am++) {
#pragma unroll
            for (int half = 0; half < 2; half++) {
                const int m = m0 + wm + am * 16 + g + half * 8;
                float2 v;
                v.x = (half ? acc[am][an].z : acc[am][an].x) + bi.x;
                v.y = (half ? acc[am][an].w : acc[am][an].y) + bi.y;
                *(float2*)(out + (size_t)m * 1024 + ng) = v;
            }
        }
    }
}

// ============================================================================
// Kernel 2: tensor-core causal flash attention — EXACT round-12 body
// (best known: pairs of 64-col kv-tiles, 2 pair-buffers, one barrier/pair).
// ============================================================================
#define KVSTR 80
#define TILEF (64*KVSTR)
#define PAIRB (2*TILEF)
#define OFF_V (2*PAIRB)
#define OFF_P (OFF_V + 2*PAIRB)
#define PSTRD 68
#define FA_SMEM_BYTES ((OFF_P + 128*PSTRD) * 4)   // 198656

__global__ void __launch_bounds__(256, 1) flash_attn_tc()
{
    extern __shared__ float sm[];
    const uint32_t smu = smem_u32(sm);
    const int tid  = threadIdx.x;
    const int lane = tid & 31;
    const int warp = tid >> 5;
    const int g  = lane >> 2;
    const int t4 = lane & 3;
    const int qt = 15 - (int)blockIdx.x;
    const int bh = blockIdx.y;
    const int q0 = qt * 128;
    const int wr = warp * 16;
    const int npair = qt + 1;

    const float* Qg = g_Q + (size_t)bh * S_ * 64;
    const float* Kg = g_K + (size_t)bh * S_ * 64;
    const float* Vg = g_V + (size_t)bh * 64 * S_;

    const int fr = tid >> 2;
    const int fc = (tid & 3) * 16;

#pragma unroll
    for (int u = 0; u < 2; u++) {
        const int kv = u * 64;
        const float* ks = Kg + (size_t)(kv + fr) * 64 + fc;
        const float* vs = Vg + (size_t)fr * 2048 + kv + fc;
        const uint32_t kd = smu + (uint32_t)(u * TILEF + fr * KVSTR + fc) * 4;
        const uint32_t vd = smu + (uint32_t)(OFF_V + u * TILEF + fr * KVSTR + fc) * 4;
#pragma unroll
        for (int j = 0; j < 4; j++) {
            cp16(kd + j * 16, ks + j * 4);
            cp16(vd + j * 16, vs + j * 4);
        }
    }
    CP_COMMIT();

    {
        const int r  = tid >> 1;
        const int c0 = (tid & 1) * 32;
        const float* src = Qg + (size_t)(q0 + r) * 64 + c0;
        float* dst = sm + OFF_P + r * PSTRD + c0;
#pragma unroll
        for (int j = 0; j < 8; j++)
            *(float4*)(dst + j * 4) = *(const float4*)(src + j * 4);
    }
    __syncthreads();

    uint32_t qf[8][4];
#pragma unroll
    for (int kk = 0; kk < 8; kk++) {
        const float* p = sm + OFF_P + (wr + g) * PSTRD + kk * 8 + t4;
        qf[kk][0] = __float_as_uint(p[0]);
        qf[kk][1] = __float_as_uint(p[8 * PSTRD]);
        qf[kk][2] = __float_as_uint(p[4]);
        qf[kk][3] = __float_as_uint(p[8 * PSTRD + 4]);
    }

    float m2[2] = {-1e30f, -1e30f};
    float l2[2] = {0.f, 0.f};
    float4 of[8];
#pragma unroll
    for (int an = 0; an < 8; an++) of[an] = make_float4(0.f, 0.f, 0.f, 0.f);

    for (int pp = 0; pp < npair; pp++) {
        CP_WAIT0();
        __syncthreads();

        if (pp + 1 < npair) {
            const int pb = (pp + 1) & 1;
#pragma unroll
            for (int u = 0; u < 2; u++) {
                const int kv = (pp + 1) * 128 + u * 64;
                const float* ks = Kg + (size_t)(kv + fr) * 64 + fc;
                const float* vs = Vg + (size_t)fr * 2048 + kv + fc;
                const uint32_t kd = smu + (uint32_t)(pb * PAIRB + u * TILEF + fr * KVSTR + fc) * 4;
                const uint32_t vd = smu + (uint32_t)(OFF_V + pb * PAIRB + u * TILEF + fr * KVSTR + fc) * 4;
#pragma unroll
                for (int j = 0; j < 4; j++) {
                    cp16(kd + j * 16, ks + j * 4);
                    cp16(vd + j * 16, vs + j * 4);
                }
            }
        }
        CP_COMMIT();

#pragma unroll
        for (int u = 0; u < 2; u++) {
            const int t   = 2 * pp + u;
            const int kv0 = t * 64;
            if (kv0 > q0 + wr + 15) continue;

            const float* smK = sm + (pp & 1) * PAIRB + u * TILEF;
            const float* smV = sm + OFF_V + (pp & 1) * PAIRB + u * TILEF;

            float4 sf[8];
#pragma unroll
            for (int an = 0; an < 8; an++) sf[an] = make_float4(0.f, 0.f, 0.f, 0.f);
#pragma unroll
            for (int b = 0; b < 4; b++) {
#pragma unroll
                for (int an = 0; an < 8; an++) {
                    const float4 kv4 = *(const float4*)(smK + (an * 8 + g) * KVSTR + 16 * b + 4 * t4);
                    mma_tf32(sf[an], qf[2*b][0], qf[2*b][1], qf[2*b][2], qf[2*b][3],
                             __float_as_uint(kv4.x), __float_as_uint(kv4.y));
                    mma_tf32(sf[an], qf[2*b+1][0], qf[2*b+1][1], qf[2*b+1][2], qf[2*b+1][3],
                             __float_as_uint(kv4.z), __float_as_uint(kv4.w));
                }
            }

            if (kv0 + 63 > q0 + wr) {
                const int r0 = q0 + wr + g;
                const int r1 = r0 + 8;
#pragma unroll
                for (int an = 0; an < 8; an++) {
                    const int col = kv0 + an * 8 + 2 * t4;
                    if (col     > r0) sf[an].x = -1e30f;
                    if (col + 1 > r0) sf[an].y = -1e30f;
                    if (col     > r1) sf[an].z = -1e30f;
                    if (col + 1 > r1) sf[an].w = -1e30f;
                }
            }

            float mt0 = -1e30f, mt1 = -1e30f;
#pragma unroll
            for (int an = 0; an < 8; an++) {
                mt0 = fmaxf(mt0, fmaxf(sf[an].x, sf[an].y));
                mt1 = fmaxf(mt1, fmaxf(sf[an].z, sf[an].w));
            }
            mt0 = fmaxf(mt0, __shfl_xor_sync(0xffffffffu, mt0, 1));
            mt0 = fmaxf(mt0, __shfl_xor_sync(0xffffffffu, mt0, 2));
            mt1 = fmaxf(mt1, __shfl_xor_sync(0xffffffffu, mt1, 1));
            mt1 = fmaxf(mt1, __shfl_xor_sync(0xffffffffu, mt1, 2));

            const float mn0 = fmaxf(m2[0], mt0);
            const float mn1 = fmaxf(m2[1], mt1);
            const float a0 = exp2p(m2[0] - mn0);
            const float a1 = exp2p(m2[1] - mn1);
            m2[0] = mn0; m2[1] = mn1;

            float s0 = 0.f, s1 = 0.f;
#pragma unroll
            for (int an = 0; an < 8; an++) {
                sf[an].x = tf32_rna(exp2p(sf[an].x - mn0));
                sf[an].y = tf32_rna(exp2p(sf[an].y - mn0));
                sf[an].z = tf32_rna(exp2p(sf[an].z - mn1));
                sf[an].w = tf32_rna(exp2p(sf[an].w - mn1));
                s0 += sf[an].x + sf[an].y;
                s1 += sf[an].z + sf[an].w;
            }
            s0 += __shfl_xor_sync(0xffffffffu, s0, 1);
            s0 += __shfl_xor_sync(0xffffffffu, s0, 2);
            s1 += __shfl_xor_sync(0xffffffffu, s1, 1);
            s1 += __shfl_xor_sync(0xffffffffu, s1, 2);
            l2[0] = l2[0] * a0 + s0;
            l2[1] = l2[1] * a1 + s1;

#pragma unroll
            for (int an = 0; an < 8; an++) {
                of[an].x *= a0; of[an].y *= a0;
                of[an].z *= a1; of[an].w *= a1;
            }

            {
                float* pp2 = sm + OFF_P + (wr + g) * PSTRD;
#pragma unroll
                for (int an = 0; an < 8; an++) {
                    *(float2*)(pp2 + an * 8 + 2 * t4) = make_float2(sf[an].x, sf[an].y);
                    *(float2*)(pp2 + 8 * PSTRD + an * 8 + 2 * t4) = make_float2(sf[an].z, sf[an].w);
                }
            }
            __syncwarp();

#pragma unroll
            for (int b = 0; b < 4; b++) {
                const float* ap = sm + OFF_P + (wr + g) * PSTRD + 16 * b + t4;
                const uint32_t A00 = __float_as_uint(ap[0]);
                const uint32_t A01 = __float_as_uint(ap[8 * PSTRD]);
                const uint32_t A02 = __float_as_uint(ap[4]);
                const uint32_t A03 = __float_as_uint(ap[8 * PSTRD + 4]);
                const uint32_t A10 = __float_as_uint(ap[8]);
                const uint32_t A11 = __float_as_uint(ap[8 * PSTRD + 8]);
                const uint32_t A12 = __float_as_uint(ap[12]);
                const uint32_t A13 = __float_as_uint(ap[8 * PSTRD + 12]);
#pragma unroll
                for (int an = 0; an < 8; an++) {
                    const float4 vv = *(const float4*)(smV + (an * 8 + g) * KVSTR + 16 * b + 4 * t4);
                    mma_tf32(of[an], A00, A01, A02, A03,
                             __float_as_uint(vv.x), __float_as_uint(vv.y));
                    mma_tf32(of[an], A10, A11, A12, A13,
                             __float_as_uint(vv.z), __float_as_uint(vv.w));
                }
            }
        }
    }

    const int b = bh >> 4;
    const int h = bh & 15;
    const float i0 = 1.0f / l2[0];
    const float i1 = 1.0f / l2[1];
    const int r0 = q0 + wr + g;
    const int r1 = r0 + 8;
    float* o0 = g_O + ((size_t)b * 2048 + r0) * 1024 + h * 64;
    float* o1 = g_O + ((size_t)b * 2048 + r1) * 1024 + h * 64;
#pragma unroll
    for (int an = 0; an < 8; an++) {
        const int c0 = an * 8 + 2 * t4;
        const int p0 = perm16(c0);
        const int p1 = perm16(c0 + 1);
        o0[p0] = tf32_rna(of[an].x * i0);
        o0[p1] = tf32_rna(of[an].y * i0);
        o1[p0] = tf32_rna(of[an].z * i1);
        o1[p1] = tf32_rna(of[an].w * i1);
    }
}

// ---------------------------------------------------------------------------
extern "C" void kernel_launch(void* const* d_in, const int* in_sizes, int n_in,
                              void* d_out, int out_size)
{
    const float* x      = (const float*)d_in[0];  // (2,2048,1024)
    const float* w_qkv  = (const float*)d_in[1];  // (3072,1024)
    const float* w_proj = (const float*)d_in[2];  // (1024,1024)
    const float* b_proj = (const float*)d_in[3];  // (1024,)
    float* out = (float*)d_out;

    cudaFuncSetAttribute(flash_attn_tc, cudaFuncAttributeMaxDynamicSharedMemorySize,
                         FA_SMEM_BYTES);
    cudaFuncSetAttribute(qkv_mma, cudaFuncAttributeMaxDynamicSharedMemorySize,
                         QKV_SMEM_BYTES);
    cudaFuncSetAttribute(proj_mma, cudaFuncAttributeMaxDynamicSharedMemorySize,
                         PROJ_SMEM_BYTES);

    round_perm_all<<<592, 256>>>(x, w_qkv, w_proj);

    qkv_mma<<<dim3(48, 32), 256, QKV_SMEM_BYTES>>>();
    flash_attn_tc<<<dim3(16, 32), 256, FA_SMEM_BYTES>>>();
    proj_mma<<<dim3(8, 32), 256, PROJ_SMEM_BYTES>>>(b_proj, out);
}

// round 16
// speedup vs baseline: 1.1002x; 1.0651x over previous
#include <cuda_runtime.h>
#include <math.h>
#include <stdint.h>

#define B_  2
#define S_  2048
#define E_  1024
#define H_  16
#define HD_ 64

// Scratch (allocation-free: __device__ globals)
__device__ float g_Q[B_*H_*S_*HD_];   // (b,h,s,d) tf32-rounded, scaled 0.125*log2(e)
__device__ float g_K[B_*H_*S_*HD_];   // (b,h,s,d) tf32-rounded, d 16-block-permuted
__device__ float g_V[B_*H_*S_*HD_];   // (b,h,d,s) TRANSPOSED, s 16-block-permuted
__device__ float g_O[B_*S_*E_];       // attention out, tf32-rounded, d 16-block-permuted
__device__ float g_Xr[B_*S_*E_];      // tf32-rounded x, k-chunk permuted
__device__ float g_Wq[3*E_*E_];       // tf32-rounded w_qkv, k-chunk permuted
__device__ float g_Wp[E_*E_];         // tf32-rounded w_proj, k-chunk permuted

// ============================================================================
// PTX helpers (plain sm_80+ ISA)
// ============================================================================
__device__ __forceinline__ float tf32_rna(float x) {
    uint32_t r;
    asm("cvt.rna.tf32.f32 %0, %1;" : "=r"(r) : "f"(x));
    return __uint_as_float(r);
}

__device__ __forceinline__ void mma_tf32(float4& d,
                                         uint32_t a0, uint32_t a1, uint32_t a2, uint32_t a3,
                                         uint32_t b0, uint32_t b1)
{
    asm volatile(
        "mma.sync.aligned.m16n8k8.row.col.f32.tf32.tf32.f32 "
        "{%0,%1,%2,%3}, {%4,%5,%6,%7}, {%8,%9}, {%0,%1,%2,%3};"
        : "+f"(d.x), "+f"(d.y), "+f"(d.z), "+f"(d.w)
        : "r"(a0), "r"(a1), "r"(a2), "r"(a3), "r"(b0), "r"(b1));
}

__device__ __forceinline__ uint32_t smem_u32(const void* p) {
    uint32_t a;
    asm("{ .reg .u64 tmp; cvta.to.shared.u64 tmp, %1; cvt.u32.u64 %0, tmp; }"
        : "=r"(a) : "l"(p));
    return a;
}

__device__ __forceinline__ void cp16(uint32_t dst, const void* src) {
    asm volatile("cp.async.cg.shared.global [%0], [%1], 16;"
                 :: "r"(dst), "l"(src) : "memory");
}
#define CP_COMMIT() asm volatile("cp.async.commit_group;" ::: "memory")
#define CP_WAIT0()  asm volatile("cp.async.wait_group 0;" ::: "memory")
#define CP_WAIT1()  asm volatile("cp.async.wait_group 1;" ::: "memory")

// 2^x in ONE MUFU instruction (full range; -1e30 underflows to exactly 0)
__device__ __forceinline__ float ex2(float x) {
    float r;
    asm("ex2.approx.f32 %0, %1;" : "=f"(r) : "f"(x));
    return r;
}

// pi(m) = (m%4)*4 + m/4 applied within a 16-aligned block (self-inverse)
__device__ __forceinline__ int perm16(int c) {
    return (c & ~15) + ((c & 3) * 4) + ((c & 15) >> 2);
}

// ============================================================================
// Pre-pass: tf32-round AND k-chunk-permute all three GEMM inputs.
// ============================================================================
#define N4_X  ((B_*S_*E_) / 4)
#define N4_WQ ((3*E_*E_) / 4)
#define N4_WP ((E_*E_) / 4)
#define N4_ALL (N4_X + N4_WQ + N4_WP)

__global__ void round_perm_all(const float* __restrict__ x,
                               const float* __restrict__ wq,
                               const float* __restrict__ wp)
{
    int f = blockIdx.x * blockDim.x + threadIdx.x;
    const int stride = gridDim.x * blockDim.x;
    for (; f < N4_ALL; f += stride) {
        const float* s;
        float4* d;
        int i = f;
        if (i < N4_X)               { s = x;  d = (float4*)g_Xr; }
        else if (i < N4_X + N4_WQ)  { i -= N4_X;         s = wq; d = (float4*)g_Wq; }
        else                        { i -= N4_X + N4_WQ; s = wp; d = (float4*)g_Wp; }
        const int t    = i & 3;
        const int base = (i >> 2) << 4;
        float4 v;
        v.x = tf32_rna(s[base + t]);
        v.y = tf32_rna(s[base + t + 4]);
        v.z = tf32_rna(s[base + t + 8]);
        v.w = tf32_rna(s[base + t + 12]);
        d[i] = v;
    }
}

// ============================================================================
// GEMM variant A (qkv, round-12 verified): CTA 128x64, 8 warps 4m x 2n,
// warp 32x32, BK=32, 3-stage cp.async, one sync per chunk, 3 CTAs/SM.
// ============================================================================
#define HALF_F 3072
#define STGF32 (2*HALF_F)
#define QKV_SMEM_BYTES (3*STGF32*4)   // 73728

__device__ __forceinline__ void qkv_fill32(uint32_t smu, const float* __restrict__ Ab,
                                           const float* __restrict__ Bb,
                                           int stage, int chunk, int tid)
{
#pragma unroll
    for (int j = 0; j < 6; j++) {
        const int o = tid + 256 * j;
        const int h = (o >> 2) & 1;
        const int r = o >> 3;
        const int q = (o & 3) * 4;
        const float* src;
        uint32_t off;
        if (r < 128) {
            src = Ab + (size_t)r * 1024 + chunk * 32 + h * 16 + q;
            off = (uint32_t)(r * 16);
        } else {
            src = Bb + (size_t)(r - 128) * 1024 + chunk * 32 + h * 16 + q;
            off = (uint32_t)(2048 + (r - 128) * 16);
        }
        cp16(smu + (uint32_t)(stage * STGF32 + h * HALF_F + off + q) * 4, src);
    }
}

#define QSCALE 0.18033688011112042f   // 0.125 * log2(e)

__global__ void __launch_bounds__(256, 3) qkv_mma()
{
    extern __shared__ float sm[];
    const uint32_t smu = smem_u32(sm);
    const int tid  = threadIdx.x;
    const int lane = tid & 31;
    const int warp = tid >> 5;
    const int wm = (warp >> 1) * 32;
    const int wn = (warp & 1) * 32;
    const int g  = lane >> 2;
    const int t  = lane & 3;
    const int m0 = blockIdx.y * 128;
    const int n0 = blockIdx.x * 64;

    const float* Ab = g_Xr + (size_t)m0 * 1024;
    const float* Bb = g_Wq + (size_t)n0 * 1024;

    float4 acc[2][4];
#pragma unroll
    for (int am = 0; am < 2; am++)
#pragma unroll
        for (int an = 0; an < 4; an++)
            acc[am][an] = make_float4(0.f, 0.f, 0.f, 0.f);

    qkv_fill32(smu, Ab, Bb, 0, 0, tid);
    CP_COMMIT();
    qkv_fill32(smu, Ab, Bb, 1, 1, tid);
    CP_COMMIT();

    int stage = 0;
    for (int c = 0; c < 32; ++c) {
        CP_WAIT1();
        __syncthreads();

        if (c + 2 < 32)
            qkv_fill32(smu, Ab, Bb, (stage + 2 >= 3 ? stage - 1 : stage + 2), c + 2, tid);
        CP_COMMIT();

#pragma unroll
        for (int h = 0; h < 2; h++) {
            const float* st = sm + stage * STGF32 + h * HALF_F;

            float4 vb[4];
#pragma unroll
            for (int an = 0; an < 4; an++)
                vb[an] = *(const float4*)(st + 2048 + (wn + an * 8 + g) * 16 + 4 * t);

            float4 vaL[2], vaH[2];
#pragma unroll
            for (int am = 0; am < 2; am++) {
                vaL[am] = *(const float4*)(st + (wm + am * 16 + g)     * 16 + 4 * t);
                vaH[am] = *(const float4*)(st + (wm + am * 16 + g + 8) * 16 + 4 * t);
            }
#pragma unroll
            for (int am = 0; am < 2; am++)
#pragma unroll
                for (int an = 0; an < 4; an++) {
                    mma_tf32(acc[am][an],
                             __float_as_uint(vaL[am].x), __float_as_uint(vaH[am].x),
                             __float_as_uint(vaL[am].y), __float_as_uint(vaH[am].y),
                             __float_as_uint(vb[an].x),  __float_as_uint(vb[an].y));
                    mma_tf32(acc[am][an],
                             __float_as_uint(vaL[am].z), __float_as_uint(vaH[am].z),
                             __float_as_uint(vaL[am].w), __float_as_uint(vaH[am].w),
                             __float_as_uint(vb[an].z),  __float_as_uint(vb[an].w));
                }
        }
        stage = (stage == 2) ? 0 : stage + 1;
    }

    // epilogue: Q natural; K d-permuted; V transposed (b,h,d,s) s-permuted
#pragma unroll
    for (int an = 0; an < 4; an++) {
        const int ng  = n0 + wn + an * 8;        // n = h*192 + sel*64 + d
        const int grp = ng >> 6;
        const int h   = grp / 3;
        const int sel = grp - 3 * h;
        const int d0  = (ng & 63) + t * 2;
        const float sc = (sel == 0) ? QSCALE : 1.0f;
#pragma unroll
        for (int am = 0; am < 2; am++) {
#pragma unroll
            for (int half = 0; half < 2; half++) {
                const int m = m0 + wm + am * 16 + g + half * 8;
                const int b = m >> 11;
                const int s = m & 2047;
                const float vx = tf32_rna((half ? acc[am][an].z : acc[am][an].x) * sc);
                const float vy = tf32_rna((half ? acc[am][an].w : acc[am][an].y) * sc);
                const size_t bh = (size_t)(b * 16 + h);
                if (sel == 0) {
                    *(float2*)(g_Q + (bh * 2048 + s) * 64 + d0) = make_float2(vx, vy);
                } else if (sel == 1) {
                    float* kp = g_K + (bh * 2048 + s) * 64;
                    kp[perm16(d0)]     = vx;
                    kp[perm16(d0 + 1)] = vy;
                } else {
                    const int sp = perm16(s);
                    float* vp = g_V + (bh * 64 + d0) * 2048;
                    vp[sp]        = vx;
                    vp[2048 + sp] = vy;
                }
            }
        }
    }
}

// ============================================================================
// GEMM variant B (proj): CTA 128x128, 8 warps 4m x 2n, warp 32x64, BK=32,
// 3-stage, 2 CTAs/SM, grid (8,32) = one wave.
// ============================================================================
#define GHALF 4096
#define GSTG  (2*GHALF)
#define PROJ_SMEM_BYTES (3*GSTG*4)      // 98304

__device__ __forceinline__ void proj_fill32(uint32_t smu, const float* __restrict__ Ab,
                                            const float* __restrict__ Bb,
                                            int stage, int chunk, int tid)
{
#pragma unroll
    for (int j = 0; j < 8; j++) {
        const int o  = tid + 256 * j;
        const int r  = o >> 3;
        const int q4 = o & 7;
        const int h  = q4 >> 2;
        const int q  = (q4 & 3) * 4;
        const float* src = (r < 128 ? Ab + (size_t)r * 1024
                                    : Bb + (size_t)(r - 128) * 1024)
                           + chunk * 32 + h * 16 + q;
        const uint32_t off = (uint32_t)(stage * GSTG + h * GHALF
                           + (r < 128 ? r * 16 : 2048 + (r - 128) * 16) + q);
        cp16(smu + off * 4, src);
    }
}

__global__ void __launch_bounds__(256, 2) proj_mma(const float* __restrict__ bias,
                                                   float* __restrict__ out)
{
    extern __shared__ float sm[];
    const uint32_t smu = smem_u32(sm);
    const int tid  = threadIdx.x;
    const int lane = tid & 31;
    const int warp = tid >> 5;
    const int wm = (warp >> 1) * 32;
    const int wn = (warp & 1) * 64;
    const int g  = lane >> 2;
    const int t  = lane & 3;
    const int m0 = blockIdx.y * 128;
    const int n0 = blockIdx.x * 128;

    const float* Ab = g_O  + (size_t)m0 * 1024;
    const float* Bb = g_Wp + (size_t)n0 * 1024;

    float4 acc[2][8];
#pragma unroll
    for (int am = 0; am < 2; am++)
#pragma unroll
        for (int an = 0; an < 8; an++)
            acc[am][an] = make_float4(0.f, 0.f, 0.f, 0.f);

    proj_fill32(smu, Ab, Bb, 0, 0, tid);
    CP_COMMIT();
    proj_fill32(smu, Ab, Bb, 1, 1, tid);
    CP_COMMIT();

    int stage = 0;
    for (int c = 0; c < 32; ++c) {
        CP_WAIT1();
        __syncthreads();

        if (c + 2 < 32)
            proj_fill32(smu, Ab, Bb, (stage + 2 >= 3 ? stage - 1 : stage + 2), c + 2, tid);
        CP_COMMIT();

#pragma unroll
        for (int h = 0; h < 2; h++) {
            const float* st = sm + stage * GSTG + h * GHALF;

            float4 vaL[2], vaH[2];
#pragma unroll
            for (int am = 0; am < 2; am++) {
                vaL[am] = *(const float4*)(st + (wm + am * 16 + g)     * 16 + 4 * t);
                vaH[am] = *(const float4*)(st + (wm + am * 16 + g + 8) * 16 + 4 * t);
            }

#pragma unroll
            for (int grp = 0; grp < 2; grp++) {
                float4 vb[4];
#pragma unroll
                for (int ax = 0; ax < 4; ax++)
                    vb[ax] = *(const float4*)(st + 2048 + (wn + (grp * 4 + ax) * 8 + g) * 16 + 4 * t);
#pragma unroll
                for (int am = 0; am < 2; am++)
#pragma unroll
                    for (int ax = 0; ax < 4; ax++) {
                        mma_tf32(acc[am][grp * 4 + ax],
                                 __float_as_uint(vaL[am].x), __float_as_uint(vaH[am].x),
                                 __float_as_uint(vaL[am].y), __float_as_uint(vaH[am].y),
                                 __float_as_uint(vb[ax].x),  __float_as_uint(vb[ax].y));
                        mma_tf32(acc[am][grp * 4 + ax],
                                 __float_as_uint(vaL[am].z), __float_as_uint(vaH[am].z),
                                 __float_as_uint(vaL[am].w), __float_as_uint(vaH[am].w),
                                 __float_as_uint(vb[ax].z),  __float_as_uint(vb[ax].w));
                    }
            }
        }
        stage = (stage == 2) ? 0 : stage + 1;
    }

#pragma unroll
    for (int an = 0; an < 8; an++) {
        const int ng = n0 + wn + an * 8 + t * 2;
        const float2 bi = *(const float2*)(bias + ng);
#pragma unroll
        for (int am = 0; am < 2; am++) {
#pragma unroll
            for (int half = 0; half < 2; half++) {
                const int m = m0 + wm + am * 16 + g + half * 8;
                float2 v;
                v.x = (half ? acc[am][an].z : acc[am][an].x) + bi.x;
                v.y = (half ? acc[am][an].w : acc[am][an].y) + bi.y;
                *(float2*)(out + (size_t)m * 1024 + ng) = v;
            }
        }
    }
}

// ============================================================================
// Kernel 2: tensor-core causal flash attention — round-12 structure, but
// softmax exp via single-instruction ex2.approx (MUFU) instead of the
// 12-op FMA polynomial: ~2560 -> ~770 softmax issue slots per SM-tile.
// ============================================================================
#define KVSTR 80
#define TILEF (64*KVSTR)
#define PAIRB (2*TILEF)
#define OFF_V (2*PAIRB)
#define OFF_P (OFF_V + 2*PAIRB)
#define PSTRD 68
#define FA_SMEM_BYTES ((OFF_P + 128*PSTRD) * 4)   // 198656

__global__ void __launch_bounds__(256, 1) flash_attn_tc()
{
    extern __shared__ float sm[];
    const uint32_t smu = smem_u32(sm);
    const int tid  = threadIdx.x;
    const int lane = tid & 31;
    const int warp = tid >> 5;
    const int g  = lane >> 2;
    const int t4 = lane & 3;
    const int qt = 15 - (int)blockIdx.x;
    const int bh = blockIdx.y;
    const int q0 = qt * 128;
    const int wr = warp * 16;
    const int npair = qt + 1;

    const float* Qg = g_Q + (size_t)bh * S_ * 64;
    const float* Kg = g_K + (size_t)bh * S_ * 64;
    const float* Vg = g_V + (size_t)bh * 64 * S_;

    const int fr = tid >> 2;
    const int fc = (tid & 3) * 16;

#pragma unroll
    for (int u = 0; u < 2; u++) {
        const int kv = u * 64;
        const float* ks = Kg + (size_t)(kv + fr) * 64 + fc;
        const float* vs = Vg + (size_t)fr * 2048 + kv + fc;
        const uint32_t kd = smu + (uint32_t)(u * TILEF + fr * KVSTR + fc) * 4;
        const uint32_t vd = smu + (uint32_t)(OFF_V + u * TILEF + fr * KVSTR + fc) * 4;
#pragma unroll
        for (int j = 0; j < 4; j++) {
            cp16(kd + j * 16, ks + j * 4);
            cp16(vd + j * 16, vs + j * 4);
        }
    }
    CP_COMMIT();

    {
        const int r  = tid >> 1;
        const int c0 = (tid & 1) * 32;
        const float* src = Qg + (size_t)(q0 + r) * 64 + c0;
        float* dst = sm + OFF_P + r * PSTRD + c0;
#pragma unroll
        for (int j = 0; j < 8; j++)
            *(float4*)(dst + j * 4) = *(const float4*)(src + j * 4);
    }
    __syncthreads();

    uint32_t qf[8][4];
#pragma unroll
    for (int kk = 0; kk < 8; kk++) {
        const float* p = sm + OFF_P + (wr + g) * PSTRD + kk * 8 + t4;
        qf[kk][0] = __float_as_uint(p[0]);
        qf[kk][1] = __float_as_uint(p[8 * PSTRD]);
        qf[kk][2] = __float_as_uint(p[4]);
        qf[kk][3] = __float_as_uint(p[8 * PSTRD + 4]);
    }

    float m2[2] = {-1e30f, -1e30f};
    float l2[2] = {0.f, 0.f};
    float4 of[8];
#pragma unroll
    for (int an = 0; an < 8; an++) of[an] = make_float4(0.f, 0.f, 0.f, 0.f);

    for (int pp = 0; pp < npair; pp++) {
        CP_WAIT0();
        __syncthreads();

        if (pp + 1 < npair) {
            const int pb = (pp + 1) & 1;
#pragma unroll
            for (int u = 0; u < 2; u++) {
                const int kv = (pp + 1) * 128 + u * 64;
                const float* ks = Kg + (size_t)(kv + fr) * 64 + fc;
                const float* vs = Vg + (size_t)fr * 2048 + kv + fc;
                const uint32_t kd = smu + (uint32_t)(pb * PAIRB + u * TILEF + fr * KVSTR + fc) * 4;
                const uint32_t vd = smu + (uint32_t)(OFF_V + pb * PAIRB + u * TILEF + fr * KVSTR + fc) * 4;
#pragma unroll
                for (int j = 0; j < 4; j++) {
                    cp16(kd + j * 16, ks + j * 4);
                    cp16(vd + j * 16, vs + j * 4);
                }
            }
        }
        CP_COMMIT();

#pragma unroll
        for (int u = 0; u < 2; u++) {
            const int t   = 2 * pp + u;
            const int kv0 = t * 64;
            if (kv0 > q0 + wr + 15) continue;

            const float* smK = sm + (pp & 1) * PAIRB + u * TILEF;
            const float* smV = sm + OFF_V + (pp & 1) * PAIRB + u * TILEF;

            float4 sf[8];
#pragma unroll
            for (int an = 0; an < 8; an++) sf[an] = make_float4(0.f, 0.f, 0.f, 0.f);
#pragma unroll
            for (int b = 0; b < 4; b++) {
#pragma unroll
                for (int an = 0; an < 8; an++) {
                    const float4 kv4 = *(const float4*)(smK + (an * 8 + g) * KVSTR + 16 * b + 4 * t4);
                    mma_tf32(sf[an], qf[2*b][0], qf[2*b][1], qf[2*b][2], qf[2*b][3],
                             __float_as_uint(kv4.x), __float_as_uint(kv4.y));
                    mma_tf32(sf[an], qf[2*b+1][0], qf[2*b+1][1], qf[2*b+1][2], qf[2*b+1][3],
                             __float_as_uint(kv4.z), __float_as_uint(kv4.w));
                }
            }

            if (kv0 + 63 > q0 + wr) {
                const int r0 = q0 + wr + g;
                const int r1 = r0 + 8;
#pragma unroll
                for (int an = 0; an < 8; an++) {
                    const int col = kv0 + an * 8 + 2 * t4;
                    if (col     > r0) sf[an].x = -1e30f;
                    if (col + 1 > r0) sf[an].y = -1e30f;
                    if (col     > r1) sf[an].z = -1e30f;
                    if (col + 1 > r1) sf[an].w = -1e30f;
                }
            }

            float mt0 = -1e30f, mt1 = -1e30f;
#pragma unroll
            for (int an = 0; an < 8; an++) {
                mt0 = fmaxf(mt0, fmaxf(sf[an].x, sf[an].y));
                mt1 = fmaxf(mt1, fmaxf(sf[an].z, sf[an].w));
            }
            mt0 = fmaxf(mt0, __shfl_xor_sync(0xffffffffu, mt0, 1));
            mt0 = fmaxf(mt0, __shfl_xor_sync(0xffffffffu, mt0, 2));
            mt1 = fmaxf(mt1, __shfl_xor_sync(0xffffffffu, mt1, 1));
            mt1 = fmaxf(mt1, __shfl_xor_sync(0xffffffffu, mt1, 2));

            const float mn0 = fmaxf(m2[0], mt0);
            const float mn1 = fmaxf(m2[1], mt1);
            const float a0 = ex2(m2[0] - mn0);
            const float a1 = ex2(m2[1] - mn1);
            m2[0] = mn0; m2[1] = mn1;

            float s0 = 0.f, s1 = 0.f;
#pragma unroll
            for (int an = 0; an < 8; an++) {
                sf[an].x = tf32_rna(ex2(sf[an].x - mn0));
                sf[an].y = tf32_rna(ex2(sf[an].y - mn0));
                sf[an].z = tf32_rna(ex2(sf[an].z - mn1));
                sf[an].w = tf32_rna(ex2(sf[an].w - mn1));
                s0 += sf[an].x + sf[an].y;
                s1 += sf[an].z + sf[an].w;
            }
            s0 += __shfl_xor_sync(0xffffffffu, s0, 1);
            s0 += __shfl_xor_sync(0xffffffffu, s0, 2);
            s1 += __shfl_xor_sync(0xffffffffu, s1, 1);
            s1 += __shfl_xor_sync(0xffffffffu, s1, 2);
            l2[0] = l2[0] * a0 + s0;
            l2[1] = l2[1] * a1 + s1;

#pragma unroll
            for (int an = 0; an < 8; an++) {
                of[an].x *= a0; of[an].y *= a0;
                of[an].z *= a1; of[an].w *= a1;
            }

            {
                float* pp2 = sm + OFF_P + (wr + g) * PSTRD;
#pragma unroll
                for (int an = 0; an < 8; an++) {
                    *(float2*)(pp2 + an * 8 + 2 * t4) = make_float2(sf[an].x, sf[an].y);
                    *(float2*)(pp2 + 8 * PSTRD + an * 8 + 2 * t4) = make_float2(sf[an].z, sf[an].w);
                }
            }
            __syncwarp();

#pragma unroll
            for (int b = 0; b < 4; b++) {
                const float* ap = sm + OFF_P + (wr + g) * PSTRD + 16 * b + t4;
                const uint32_t A00 = __float_as_uint(ap[0]);
                const uint32_t A01 = __float_as_uint(ap[8 * PSTRD]);
                const uint32_t A02 = __float_as_uint(ap[4]);
                const uint32_t A03 = __float_as_uint(ap[8 * PSTRD + 4]);
                const uint32_t A10 = __float_as_uint(ap[8]);
                const uint32_t A11 = __float_as_uint(ap[8 * PSTRD + 8]);
                const uint32_t A12 = __float_as_uint(ap[12]);
                const uint32_t A13 = __float_as_uint(ap[8 * PSTRD + 12]);
#pragma unroll
                for (int an = 0; an < 8; an++) {
                    const float4 vv = *(const float4*)(smV + (an * 8 + g) * KVSTR + 16 * b + 4 * t4);
                    mma_tf32(of[an], A00, A01, A02, A03,
                             __float_as_uint(vv.x), __float_as_uint(vv.y));
                    mma_tf32(of[an], A10, A11, A12, A13,
                             __float_as_uint(vv.z), __float_as_uint(vv.w));
                }
            }
        }
    }

    const int b = bh >> 4;
    const int h = bh & 15;
    const float i0 = 1.0f / l2[0];
    const float i1 = 1.0f / l2[1];
    const int r0 = q0 + wr + g;
    const int r1 = r0 + 8;
    float* o0 = g_O + ((size_t)b * 2048 + r0) * 1024 + h * 64;
    float* o1 = g_O + ((size_t)b * 2048 + r1) * 1024 + h * 64;
#pragma unroll
    for (int an = 0; an < 8; an++) {
        const int c0 = an * 8 + 2 * t4;
        const int p0 = perm16(c0);
        const int p1 = perm16(c0 + 1);
        o0[p0] = tf32_rna(of[an].x * i0);
        o0[p1] = tf32_rna(of[an].y * i0);
        o1[p0] = tf32_rna(of[an].z * i1);
        o1[p1] = tf32_rna(of[an].w * i1);
    }
}

// ---------------------------------------------------------------------------
extern "C" void kernel_launch(void* const* d_in, const int* in_sizes, int n_in,
                              void* d_out, int out_size)
{
    const float* x      = (const float*)d_in[0];  // (2,2048,1024)
    const float* w_qkv  = (const float*)d_in[1];  // (3072,1024)
    const float* w_proj = (const float*)d_in[2];  // (1024,1024)
    const float* b_proj = (const float*)d_in[3];  // (1024,)
    float* out = (float*)d_out;

    cudaFuncSetAttribute(flash_attn_tc, cudaFuncAttributeMaxDynamicSharedMemorySize,
                         FA_SMEM_BYTES);
    cudaFuncSetAttribute(qkv_mma, cudaFuncAttributeMaxDynamicSharedMemorySize,
                         QKV_SMEM_BYTES);
    cudaFuncSetAttribute(proj_mma, cudaFuncAttributeMaxDynamicSharedMemorySize,
                         PROJ_SMEM_BYTES);

    round_perm_all<<<592, 256>>>(x, w_qkv, w_proj);

    qkv_mma<<<dim3(48, 32), 256, QKV_SMEM_BYTES>>>();
    flash_attn_tc<<<dim3(16, 32), 256, FA_SMEM_BYTES>>>();
    proj_mma<<<dim3(8, 32), 256, PROJ_SMEM_BYTES>>>(b_proj, out);
}